// round 1
// baseline (speedup 1.0000x reference)
#include <cuda_runtime.h>
#include <math.h>

#define EMBED 1024
#define HEADS 16
#define HDIM  64
#define BATCH 2
#define SEQ   2048
#define MTOT  (BATCH*SEQ)   // 4096

// Scratch (device globals: no allocation allowed)
__device__ float g_Q[MTOT*EMBED];
__device__ float g_K[MTOT*EMBED];
__device__ float g_V[MTOT*EMBED];
__device__ float g_AO[MTOT*EMBED];

// ---------------------------------------------------------------------------
// GEMM: C[M,N] = A[M,K] @ W[K,N] + bias[N]   (row-major, all dims % 128 == 0)
// 128x128 tile, BK=8, 256 threads, 8x8 per-thread register blocking.
// ---------------------------------------------------------------------------
__global__ __launch_bounds__(256) void gemm_bias(
    const float* __restrict__ A, const float* __restrict__ W,
    const float* __restrict__ bias, float* __restrict__ C,
    int M, int N, int K)
{
    __shared__ float As[8][128];
    __shared__ float Bs[8][128];

    int tid = threadIdx.x;
    int bm = blockIdx.y * 128;
    int bn = blockIdx.x * 128;

    int arow = tid >> 1;           // 0..127
    int acol = (tid & 1) * 4;      // 0 or 4
    int brow = tid >> 5;           // 0..7
    int bcol = (tid & 31) * 4;     // 0..124
    int tx = tid & 15;             // 0..15
    int ty = tid >> 4;             // 0..15

    float acc[8][8];
#pragma unroll
    for (int i = 0; i < 8; i++)
#pragma unroll
        for (int j = 0; j < 8; j++) acc[i][j] = 0.f;

    const float* Aptr = A + (size_t)(bm + arow) * K + acol;
    const float* Wptr = W + (size_t)brow * N + bn + bcol;

    for (int k0 = 0; k0 < K; k0 += 8) {
        float4 av = *(const float4*)(Aptr + k0);
        float4 bv = *(const float4*)(Wptr + (size_t)k0 * N);
        As[acol + 0][arow] = av.x;
        As[acol + 1][arow] = av.y;
        As[acol + 2][arow] = av.z;
        As[acol + 3][arow] = av.w;
        *(float4*)&Bs[brow][bcol] = bv;
        __syncthreads();

#pragma unroll
        for (int kk = 0; kk < 8; kk++) {
            float ra[8], rb[8];
            *(float4*)&ra[0] = *(const float4*)&As[kk][ty * 8];
            *(float4*)&ra[4] = *(const float4*)&As[kk][ty * 8 + 4];
            *(float4*)&rb[0] = *(const float4*)&Bs[kk][tx * 8];
            *(float4*)&rb[4] = *(const float4*)&Bs[kk][tx * 8 + 4];
#pragma unroll
            for (int i = 0; i < 8; i++)
#pragma unroll
                for (int j = 0; j < 8; j++)
                    acc[i][j] += ra[i] * rb[j];
        }
        __syncthreads();
    }

    float bb[8];
    *(float4*)&bb[0] = *(const float4*)&bias[bn + tx * 8];
    *(float4*)&bb[4] = *(const float4*)&bias[bn + tx * 8 + 4];

#pragma unroll
    for (int i = 0; i < 8; i++) {
        size_t row = (size_t)(bm + ty * 8 + i);
        float4 o0, o1;
        o0.x = acc[i][0] + bb[0]; o0.y = acc[i][1] + bb[1];
        o0.z = acc[i][2] + bb[2]; o0.w = acc[i][3] + bb[3];
        o1.x = acc[i][4] + bb[4]; o1.y = acc[i][5] + bb[5];
        o1.z = acc[i][6] + bb[6]; o1.w = acc[i][7] + bb[7];
        *(float4*)&C[row * N + bn + tx * 8]     = o0;
        *(float4*)&C[row * N + bn + tx * 8 + 4] = o1;
    }
}

// ---------------------------------------------------------------------------
// Flash attention (fp32): per block = one (b,h) and 128 query rows.
// BN=64 key tile, online softmax, P staged via smem.
// Thread layout: rowg = tid>>3 (4 rows each), colg = tid&7
//   scores: cols = colg + 8*j (j=0..7); O dims: colg*8 + dd (dd=0..7).
// smem stride 68 floats for bank-conflict-free float4 access.
// ---------------------------------------------------------------------------
#define FBM 128
#define FBN 64
#define SSTR 68
#define FLASH_SMEM_BYTES ((FBM*SSTR + FBN*SSTR + FBN*SSTR + FBM*SSTR) * 4)

extern __shared__ float fsm[];

__global__ __launch_bounds__(256) void flash_attn(
    const float* __restrict__ Q, const float* __restrict__ K,
    const float* __restrict__ V, float* __restrict__ O)
{
    float* Qs = fsm;                    // [128][68]
    float* Ks = Qs + FBM * SSTR;        // [64][68]
    float* Vs = Ks + FBN * SSTR;        // [64][68]
    float* Ps = Vs + FBN * SSTR;        // [128][68]

    int tid = threadIdx.x;
    int qt = blockIdx.x, h = blockIdx.y, b = blockIdx.z;

    const float* Qg = Q + ((size_t)(b * SEQ + qt * FBM)) * EMBED + h * HDIM;
    const float* Kg = K + (size_t)b * SEQ * EMBED + h * HDIM;
    const float* Vg = V + (size_t)b * SEQ * EMBED + h * HDIM;

    const float qscale = 0.125f;  // 1/sqrt(64)

    // Load Q tile (scaled): 128x64 floats
#pragma unroll
    for (int i = 0; i < 8; i++) {
        int e = tid + i * 256;
        int r = e >> 4, c = (e & 15) * 4;
        float4 v = *(const float4*)&Qg[(size_t)r * EMBED + c];
        v.x *= qscale; v.y *= qscale; v.z *= qscale; v.w *= qscale;
        *(float4*)&Qs[r * SSTR + c] = v;
    }

    int rowg = tid >> 3;   // 0..31
    int colg = tid & 7;    // 0..7

    float m[4], l[4], o[4][8];
#pragma unroll
    for (int r = 0; r < 4; r++) {
        m[r] = -1e30f; l[r] = 0.f;
#pragma unroll
        for (int d = 0; d < 8; d++) o[r][d] = 0.f;
    }

    for (int kt = 0; kt < SEQ / FBN; kt++) {
        __syncthreads();   // previous PV reads done before overwriting K/V
        // Load K,V tiles: 64x64 each
#pragma unroll
        for (int i = 0; i < 4; i++) {
            int e = tid + i * 256;
            int r = e >> 4, c = (e & 15) * 4;
            *(float4*)&Ks[r * SSTR + c] =
                *(const float4*)&Kg[(size_t)(kt * FBN + r) * EMBED + c];
            *(float4*)&Vs[r * SSTR + c] =
                *(const float4*)&Vg[(size_t)(kt * FBN + r) * EMBED + c];
        }
        __syncthreads();

        // Scores: s[r][j] = Qs[row] . Ks[col]
        float s[4][8];
#pragma unroll
        for (int r = 0; r < 4; r++)
#pragma unroll
            for (int j = 0; j < 8; j++) s[r][j] = 0.f;

#pragma unroll
        for (int d4 = 0; d4 < 16; d4++) {
            float4 q[4];
#pragma unroll
            for (int r = 0; r < 4; r++)
                q[r] = *(const float4*)&Qs[(rowg * 4 + r) * SSTR + d4 * 4];
#pragma unroll
            for (int j = 0; j < 8; j++) {
                float4 kv = *(const float4*)&Ks[(colg + 8 * j) * SSTR + d4 * 4];
#pragma unroll
                for (int r = 0; r < 4; r++)
                    s[r][j] += q[r].x * kv.x + q[r].y * kv.y
                             + q[r].z * kv.z + q[r].w * kv.w;
            }
        }

        // Online softmax
#pragma unroll
        for (int r = 0; r < 4; r++) {
            float mx = s[r][0];
#pragma unroll
            for (int j = 1; j < 8; j++) mx = fmaxf(mx, s[r][j]);
            mx = fmaxf(mx, __shfl_xor_sync(0xffffffffu, mx, 1));
            mx = fmaxf(mx, __shfl_xor_sync(0xffffffffu, mx, 2));
            mx = fmaxf(mx, __shfl_xor_sync(0xffffffffu, mx, 4));
            float mn = fmaxf(m[r], mx);
            float corr = __expf(m[r] - mn);
            m[r] = mn;
            float rs = 0.f;
#pragma unroll
            for (int j = 0; j < 8; j++) {
                float p = __expf(s[r][j] - mn);
                s[r][j] = p;
                rs += p;
            }
            rs += __shfl_xor_sync(0xffffffffu, rs, 1);
            rs += __shfl_xor_sync(0xffffffffu, rs, 2);
            rs += __shfl_xor_sync(0xffffffffu, rs, 4);
            l[r] = l[r] * corr + rs;
#pragma unroll
            for (int d = 0; d < 8; d++) o[r][d] *= corr;
            // stage P to smem
#pragma unroll
            for (int j = 0; j < 8; j++)
                Ps[(rowg * 4 + r) * SSTR + colg + 8 * j] = s[r][j];
        }
        __syncthreads();

        // O += P @ V  (dims colg*8 .. colg*8+7)
#pragma unroll
        for (int j4 = 0; j4 < 16; j4++) {
            float p4[4][4];
#pragma unroll
            for (int r = 0; r < 4; r++)
                *(float4*)p4[r] = *(const float4*)&Ps[(rowg * 4 + r) * SSTR + j4 * 4];
#pragma unroll
            for (int jj = 0; jj < 4; jj++) {
                int j = j4 * 4 + jj;
                float4 v0 = *(const float4*)&Vs[j * SSTR + colg * 8];
                float4 v1 = *(const float4*)&Vs[j * SSTR + colg * 8 + 4];
#pragma unroll
                for (int r = 0; r < 4; r++) {
                    float p = p4[r][jj];
                    o[r][0] += p * v0.x; o[r][1] += p * v0.y;
                    o[r][2] += p * v0.z; o[r][3] += p * v0.w;
                    o[r][4] += p * v1.x; o[r][5] += p * v1.y;
                    o[r][6] += p * v1.z; o[r][7] += p * v1.w;
                }
            }
        }
    }

    // Epilogue: O normalized, layout [B*S, E] at column h*64
    float* Og = O + ((size_t)(b * SEQ + qt * FBM)) * EMBED + h * HDIM;
#pragma unroll
    for (int r = 0; r < 4; r++) {
        float inv = 1.f / l[r];
        float4 a0, a1;
        a0.x = o[r][0] * inv; a0.y = o[r][1] * inv;
        a0.z = o[r][2] * inv; a0.w = o[r][3] * inv;
        a1.x = o[r][4] * inv; a1.y = o[r][5] * inv;
        a1.z = o[r][6] * inv; a1.w = o[r][7] * inv;
        size_t row = (size_t)(rowg * 4 + r);
        *(float4*)&Og[row * EMBED + colg * 8]     = a0;
        *(float4*)&Og[row * EMBED + colg * 8 + 4] = a1;
    }
}

// ---------------------------------------------------------------------------
extern "C" void kernel_launch(void* const* d_in, const int* in_sizes, int n_in,
                              void* d_out, int out_size)
{
    const float* x  = (const float*)d_in[0];
    const float* Wq = (const float*)d_in[1];
    const float* bq = (const float*)d_in[2];
    const float* Wk = (const float*)d_in[3];
    const float* bk = (const float*)d_in[4];
    const float* Wv = (const float*)d_in[5];
    const float* bv = (const float*)d_in[6];
    const float* Wo = (const float*)d_in[7];
    const float* bo = (const float*)d_in[8];
    float* out = (float*)d_out;

    float *pQ, *pK, *pV, *pAO;
    cudaGetSymbolAddress((void**)&pQ,  g_Q);
    cudaGetSymbolAddress((void**)&pK,  g_K);
    cudaGetSymbolAddress((void**)&pV,  g_V);
    cudaGetSymbolAddress((void**)&pAO, g_AO);

    cudaFuncSetAttribute(flash_attn,
                         cudaFuncAttributeMaxDynamicSharedMemorySize,
                         FLASH_SMEM_BYTES);

    dim3 gg(EMBED / 128, MTOT / 128);   // (8, 32)
    gemm_bias<<<gg, 256>>>(x, Wq, bq, pQ, MTOT, EMBED, EMBED);
    gemm_bias<<<gg, 256>>>(x, Wk, bk, pK, MTOT, EMBED, EMBED);
    gemm_bias<<<gg, 256>>>(x, Wv, bv, pV, MTOT, EMBED, EMBED);

    flash_attn<<<dim3(SEQ / FBM, HEADS, BATCH), 256, FLASH_SMEM_BYTES>>>(
        pQ, pK, pV, pAO);

    gemm_bias<<<gg, 256>>>(pAO, Wo, bo, out, MTOT, EMBED, EMBED);
}

// round 5
// speedup vs baseline: 2.7347x; 2.7347x over previous
#include <cuda_runtime.h>
#include <cuda_bf16.h>
#include <math.h>
#include <stdint.h>

#define EMBED 1024
#define HEADS 16
#define HDIM  64
#define BATCH 2
#define SEQ   2048
#define MTOT  (BATCH*SEQ)   // 4096

// ---------------- scratch (device globals; no allocation allowed) ----------
__device__ __nv_bfloat16 g_xh[MTOT*EMBED],  g_xl[MTOT*EMBED];
__device__ __nv_bfloat16 g_wth[4][EMBED*EMBED];
__device__ __nv_bfloat16 g_wtl[4][EMBED*EMBED];
__device__ __nv_bfloat16 g_qh[MTOT*EMBED], g_ql[MTOT*EMBED];
__device__ __nv_bfloat16 g_kh[MTOT*EMBED], g_kl[MTOT*EMBED];
__device__ __nv_bfloat16 g_vh[MTOT*EMBED], g_vl[MTOT*EMBED];
__device__ __nv_bfloat16 g_aoh[MTOT*EMBED], g_aol[MTOT*EMBED];

// ---------------- baseline-ISA PTX helpers (no sm_103a features!) ----------
__device__ __forceinline__ uint32_t smem_u32(const void* p) {
    uint32_t a;
    asm("{ .reg .u64 t; cvta.to.shared.u64 t, %1; cvt.u32.u64 %0, t; }"
        : "=r"(a) : "l"(p));
    return a;
}
__device__ __forceinline__ void ldsm4(uint32_t* r, uint32_t addr) {
    asm volatile("ldmatrix.sync.aligned.m8n8.x4.shared.b16 {%0,%1,%2,%3}, [%4];"
        : "=r"(r[0]), "=r"(r[1]), "=r"(r[2]), "=r"(r[3]) : "r"(addr));
}
__device__ __forceinline__ void ldsm4t(uint32_t* r, uint32_t addr) {
    asm volatile("ldmatrix.sync.aligned.m8n8.x4.trans.shared.b16 {%0,%1,%2,%3}, [%4];"
        : "=r"(r[0]), "=r"(r[1]), "=r"(r[2]), "=r"(r[3]) : "r"(addr));
}
__device__ __forceinline__ void mma16816(float* c, const uint32_t* a,
                                         uint32_t b0, uint32_t b1) {
    asm volatile("mma.sync.aligned.m16n8k16.row.col.f32.bf16.bf16.f32 "
        "{%0,%1,%2,%3}, {%4,%5,%6,%7}, {%8,%9}, {%0,%1,%2,%3};"
        : "+f"(c[0]), "+f"(c[1]), "+f"(c[2]), "+f"(c[3])
        : "r"(a[0]), "r"(a[1]), "r"(a[2]), "r"(a[3]), "r"(b0), "r"(b1));
}
__device__ __forceinline__ void cpa16(uint32_t dst, const void* src) {
    asm volatile("cp.async.cg.shared.global [%0], [%1], 16;"
                 :: "r"(dst), "l"(src));
}
#define CP_COMMIT() asm volatile("cp.async.commit_group;" ::: "memory")
#define CP_WAIT1()  asm volatile("cp.async.wait_group 1;" ::: "memory")
#define CP_WAIT0()  asm volatile("cp.async.wait_group 0;" ::: "memory")

// swizzled smem offset inside a 128B-row tile: (row, 16B-chunk)
#define SWADDR(base, row, chk) ((base) + (row)*128 + ((((chk) ^ ((row)&7))) << 4))

// split two fp32 -> packed bf16x2 hi + lo
__device__ __forceinline__ void split2(float v0, float v1,
                                       uint32_t& hi, uint32_t& lo) {
    __nv_bfloat16 h0 = __float2bfloat16(v0), h1 = __float2bfloat16(v1);
    float r0 = v0 - __bfloat162float(h0);
    float r1 = v1 - __bfloat162float(h1);
    __nv_bfloat162 H; H.x = h0; H.y = h1;
    __nv_bfloat162 L; L.x = __float2bfloat16(r0); L.y = __float2bfloat16(r1);
    hi = *(uint32_t*)&H;
    lo = *(uint32_t*)&L;
}

// ---------------------------------------------------------------------------
// prep: split fp32 -> bf16 hi/lo; transpose+split weights
// ---------------------------------------------------------------------------
__global__ __launch_bounds__(256) void split_f32(
    const float* __restrict__ src, __nv_bfloat16* __restrict__ hi,
    __nv_bfloat16* __restrict__ lo, int n4)
{
    int i = blockIdx.x * 256 + threadIdx.x;
    if (i >= n4) return;
    float4 v = ((const float4*)src)[i];
    uint32_t h01, l01, h23, l23;
    split2(v.x, v.y, h01, l01);
    split2(v.z, v.w, h23, l23);
    uint2 H = {h01, h23}, L = {l01, l23};
    ((uint2*)hi)[i] = H;
    ((uint2*)lo)[i] = L;
}

__global__ __launch_bounds__(256) void transpose_split(
    const float* __restrict__ W, __nv_bfloat16* __restrict__ Th,
    __nv_bfloat16* __restrict__ Tl)
{
    __shared__ float t[32][33];
    int n0 = blockIdx.x * 32, k0 = blockIdx.y * 32;
    int tx = threadIdx.x, ty = threadIdx.y;
#pragma unroll
    for (int i = 0; i < 4; i++) {
        int k = ty + i * 8;
        t[k][tx] = W[(size_t)(k0 + k) * EMBED + n0 + tx];
    }
    __syncthreads();
#pragma unroll
    for (int i = 0; i < 4; i++) {
        int n = ty + i * 8;
        float v = t[tx][n];
        __nv_bfloat16 h = __float2bfloat16(v);
        __nv_bfloat16 l = __float2bfloat16(v - __bfloat162float(h));
        size_t o = (size_t)(n0 + n) * EMBED + k0 + tx;
        Th[o] = h;
        Tl[o] = l;
    }
}

// ---------------------------------------------------------------------------
// GEMM via mma.sync bf16 split:  C[M,N] = (Ah+Al) @ (Bh+Bl)^T + bias
// A [M,K] row-major; B given as Wt [N,K] row-major (= col-major K x N).
// CTA 128x128, BK=64, 512 threads (16 warps, 4x4), 2-stage cp.async.
// smem/stage: Ah Al Bh Bl, each 128x128B = 16KB -> 64KB; x2 = 128KB.
// Output: fp32 (Cf) or split bf16 (Ch, Cl).
// ---------------------------------------------------------------------------
#define GEMM_SMEM (2 * 65536)
extern __shared__ char dynsm[];

__global__ __launch_bounds__(512, 1) void gemm_mma(
    const __nv_bfloat16* __restrict__ Ah, const __nv_bfloat16* __restrict__ Al,
    const __nv_bfloat16* __restrict__ Bh, const __nv_bfloat16* __restrict__ Bl,
    const float* __restrict__ bias, float* __restrict__ Cf,
    __nv_bfloat16* __restrict__ Ch, __nv_bfloat16* __restrict__ Cl,
    int M, int N, int K)
{
    uint32_t sb = smem_u32(dynsm);
    int tid = threadIdx.x;
    int lane = tid & 31, w = tid >> 5;
    int wm = w >> 2, wn = w & 3;
    int bm = blockIdx.y * 128, bn = blockIdx.x * 128;

    const __nv_bfloat16* tiles[4] = {Ah, Al, Bh, Bl};

    // async load of one K-chunk (ci) into stage st
    auto load_chunk = [&](int ci, int st) {
        uint32_t stb = sb + st * 65536;
#pragma unroll
        for (int rep = 0; rep < 8; rep++) {
            int idx = rep * 512 + tid;
            int tile = idx >> 10;
            int row = (idx >> 3) & 127;
            int c = idx & 7;
            int grow = (tile < 2 ? bm : bn) + row;
            const char* src = (const char*)tiles[tile]
                + ((size_t)grow * K + ci * 64) * 2 + c * 16;
            cpa16(SWADDR(stb + tile * 16384, row, c), src);
        }
        CP_COMMIT();
    };

    float acc[2][4][4];
#pragma unroll
    for (int a = 0; a < 2; a++)
#pragma unroll
        for (int b = 0; b < 4; b++)
#pragma unroll
            for (int c = 0; c < 4; c++) acc[a][b][c] = 0.f;

    const int NCH = K / 64;   // 16
    load_chunk(0, 0);
    load_chunk(1, 1);

    for (int i = 0; i < NCH; i++) {
        if (i < NCH - 1) CP_WAIT1(); else CP_WAIT0();
        __syncthreads();
        uint32_t stb = sb + (i & 1) * 65536;
        uint32_t sAh = stb, sAl = stb + 16384, sBh = stb + 32768, sBl = stb + 49152;

#pragma unroll
        for (int ks = 0; ks < 4; ks++) {
            int chk = ks * 2 + (lane >> 4);
            uint32_t ah[2][4], al[2][4];
#pragma unroll
            for (int ma = 0; ma < 2; ma++) {
                int r = wm * 32 + ma * 16 + (lane & 15);
                ldsm4(ah[ma], SWADDR(sAh, r, chk));
                ldsm4(al[ma], SWADDR(sAl, r, chk));
            }
#pragma unroll
            for (int ng = 0; ng < 2; ng++) {
                int br = wn * 32 + ng * 16 + (lane & 15);
                uint32_t bh[4], bl[4];
                ldsm4(bh, SWADDR(sBh, br, chk));
                ldsm4(bl, SWADDR(sBl, br, chk));
#pragma unroll
                for (int ma = 0; ma < 2; ma++) {
                    float* c0 = acc[ma][ng * 2 + 0];
                    float* c1 = acc[ma][ng * 2 + 1];
                    mma16816(c0, ah[ma], bh[0], bh[2]);
                    mma16816(c0, ah[ma], bl[0], bl[2]);
                    mma16816(c0, al[ma], bh[0], bh[2]);
                    mma16816(c1, ah[ma], bh[1], bh[3]);
                    mma16816(c1, ah[ma], bl[1], bl[3]);
                    mma16816(c1, al[ma], bh[1], bh[3]);
                }
            }
        }
        __syncthreads();
        if (i + 2 < NCH) load_chunk(i + 2, i & 1);
    }

    // epilogue
#pragma unroll
    for (int na = 0; na < 4; na++) {
        int col = bn + wn * 32 + na * 8 + (lane & 3) * 2;
        float b0 = bias[col], b1 = bias[col + 1];
#pragma unroll
        for (int ma = 0; ma < 2; ma++) {
            int row0 = bm + wm * 32 + ma * 16 + (lane >> 2);
#pragma unroll
            for (int ri = 0; ri < 2; ri++) {
                int row = row0 + ri * 8;
                float v0 = acc[ma][na][ri * 2 + 0] + b0;
                float v1 = acc[ma][na][ri * 2 + 1] + b1;
                size_t off = (size_t)row * N + col;
                if (Cf) {
                    float2 o = {v0, v1};
                    *(float2*)&Cf[off] = o;
                } else {
                    uint32_t hi, lo;
                    split2(v0, v1, hi, lo);
                    *(uint32_t*)&Ch[off] = hi;
                    *(uint32_t*)&Cl[off] = lo;
                }
            }
        }
    }
}

// ---------------------------------------------------------------------------
// Flash attention via mma.sync bf16 split.
// CTA: 128 q-rows of one (b,h); 256 threads, 8 warps; warp = 16 rows.
// Key blocks of 64; Q resident, K/V double-buffered via cp.async.
// S-frags (fp32) -> softmax -> P frags feed PV mma directly from registers.
// smem: Qh 16K | Ql 16K | 2 stages x (Kh Kl Vh Vl, 8K each) = 96KB.
// ---------------------------------------------------------------------------
#define FL_SMEM (32768 + 2 * 32768)

__global__ __launch_bounds__(256) void flash_mma(
    const __nv_bfloat16* __restrict__ Qh, const __nv_bfloat16* __restrict__ Ql,
    const __nv_bfloat16* __restrict__ Kh, const __nv_bfloat16* __restrict__ Kl,
    const __nv_bfloat16* __restrict__ Vh, const __nv_bfloat16* __restrict__ Vl,
    __nv_bfloat16* __restrict__ Oh, __nv_bfloat16* __restrict__ Ol)
{
    uint32_t sb = smem_u32(dynsm);
    int tid = threadIdx.x;
    int lane = tid & 31, w = tid >> 5;
    int qt = blockIdx.x, h = blockIdx.y, b = blockIdx.z;
    int qrow0 = b * SEQ + qt * 128;
    int krow0 = b * SEQ;
    size_t hoff = (size_t)h * HDIM;

    uint32_t sQh = sb, sQl = sb + 16384;

    const __nv_bfloat16* kvsrc[4] = {Kh, Kl, Vh, Vl};

    auto load_kv = [&](int kb, int st) {
        uint32_t stb = sb + 32768 + st * 32768;
#pragma unroll
        for (int rep = 0; rep < 8; rep++) {
            int idx = rep * 256 + tid;
            int tile = idx >> 9;
            int row = (idx >> 3) & 63;
            int c = idx & 7;
            const char* src = (const char*)kvsrc[tile]
                + ((size_t)(krow0 + kb * 64 + row) * EMBED + hoff) * 2 + c * 16;
            cpa16(SWADDR(stb + tile * 8192, row, c), src);
        }
        CP_COMMIT();
    };

    // group 0: Q + KV block 0
    {
#pragma unroll
        for (int rep = 0; rep < 8; rep++) {
            int idx = rep * 256 + tid;
            int tile = idx >> 10;            // 0 = Qh, 1 = Ql
            int row = (idx >> 3) & 127;
            int c = idx & 7;
            const char* src = (const char*)(tile ? Ql : Qh)
                + ((size_t)(qrow0 + row) * EMBED + hoff) * 2 + c * 16;
            cpa16(SWADDR(sb + tile * 16384, row, c), src);
        }
#pragma unroll
        for (int rep = 0; rep < 8; rep++) {
            int idx = rep * 256 + tid;
            int tile = idx >> 9;
            int row = (idx >> 3) & 63;
            int c = idx & 7;
            const char* src = (const char*)kvsrc[tile]
                + ((size_t)(krow0 + row) * EMBED + hoff) * 2 + c * 16;
            cpa16(SWADDR(sb + 32768 + tile * 8192, row, c), src);
        }
        CP_COMMIT();
    }
    load_kv(1, 1);

    float o[8][4];
#pragma unroll
    for (int a = 0; a < 8; a++)
#pragma unroll
        for (int c = 0; c < 4; c++) o[a][c] = 0.f;
    float m0 = -1e30f, m1 = -1e30f, l0 = 0.f, l1 = 0.f;

    const int NKB = SEQ / 64;   // 32
    for (int kb = 0; kb < NKB; kb++) {
        if (kb < NKB - 1) CP_WAIT1(); else CP_WAIT0();
        __syncthreads();
        uint32_t stb = sb + 32768 + (kb & 1) * 32768;
        uint32_t sKh = stb, sKl = stb + 8192, sVh = stb + 16384, sVl = stb + 24576;

        // ---- S = Qh Kh' + Qh Kl' + Ql Kh'  (warp rows w*16..+15, keys 0..63)
        float s[8][4];
#pragma unroll
        for (int a = 0; a < 8; a++)
#pragma unroll
            for (int c = 0; c < 4; c++) s[a][c] = 0.f;

#pragma unroll
        for (int ks = 0; ks < 4; ks++) {
            int chk = ks * 2 + (lane >> 4);
            int ar = w * 16 + (lane & 15);
            uint32_t qh[4], ql[4];
            ldsm4(qh, SWADDR(sQh, ar, chk));
            ldsm4(ql, SWADDR(sQl, ar, chk));
#pragma unroll
            for (int np = 0; np < 4; np++) {
                int br = np * 16 + (lane & 15);
                uint32_t bh[4], bl[4];
                ldsm4(bh, SWADDR(sKh, br, chk));
                ldsm4(bl, SWADDR(sKl, br, chk));
                float* c0 = s[np * 2 + 0];
                float* c1 = s[np * 2 + 1];
                mma16816(c0, qh, bh[0], bh[2]);
                mma16816(c0, qh, bl[0], bl[2]);
                mma16816(c0, ql, bh[0], bh[2]);
                mma16816(c1, qh, bh[1], bh[3]);
                mma16816(c1, qh, bl[1], bl[3]);
                mma16816(c1, ql, bh[1], bh[3]);
            }
        }

        // ---- online softmax (rows: lane>>2 and +8; scale 1/8 exact) -------
#pragma unroll
        for (int a = 0; a < 8; a++)
#pragma unroll
            for (int c = 0; c < 4; c++) s[a][c] *= 0.125f;

        float mx0 = -1e30f, mx1 = -1e30f;
#pragma unroll
        for (int a = 0; a < 8; a++) {
            mx0 = fmaxf(mx0, fmaxf(s[a][0], s[a][1]));
            mx1 = fmaxf(mx1, fmaxf(s[a][2], s[a][3]));
        }
        mx0 = fmaxf(mx0, __shfl_xor_sync(0xffffffffu, mx0, 1));
        mx0 = fmaxf(mx0, __shfl_xor_sync(0xffffffffu, mx0, 2));
        mx1 = fmaxf(mx1, __shfl_xor_sync(0xffffffffu, mx1, 1));
        mx1 = fmaxf(mx1, __shfl_xor_sync(0xffffffffu, mx1, 2));
        float mn0 = fmaxf(m0, mx0), mn1 = fmaxf(m1, mx1);
        float cr0 = __expf(m0 - mn0), cr1 = __expf(m1 - mn1);
        m0 = mn0; m1 = mn1;
        float sum0 = 0.f, sum1 = 0.f;
#pragma unroll
        for (int a = 0; a < 8; a++) {
            s[a][0] = __expf(s[a][0] - mn0); sum0 += s[a][0];
            s[a][1] = __expf(s[a][1] - mn0); sum0 += s[a][1];
            s[a][2] = __expf(s[a][2] - mn1); sum1 += s[a][2];
            s[a][3] = __expf(s[a][3] - mn1); sum1 += s[a][3];
        }
        sum0 += __shfl_xor_sync(0xffffffffu, sum0, 1);
        sum0 += __shfl_xor_sync(0xffffffffu, sum0, 2);
        sum1 += __shfl_xor_sync(0xffffffffu, sum1, 1);
        sum1 += __shfl_xor_sync(0xffffffffu, sum1, 2);
        l0 = l0 * cr0 + sum0;
        l1 = l1 * cr1 + sum1;
#pragma unroll
        for (int a = 0; a < 8; a++) {
            o[a][0] *= cr0; o[a][1] *= cr0;
            o[a][2] *= cr1; o[a][3] *= cr1;
        }

        // ---- O += (Ph + Pl) (Vh + Vl): per key k16-step build P frags -----
#pragma unroll
        for (int ks = 0; ks < 4; ks++) {
            uint32_t aph[4], apl[4];
            split2(s[2 * ks][0],     s[2 * ks][1],     aph[0], apl[0]);
            split2(s[2 * ks][2],     s[2 * ks][3],     aph[1], apl[1]);
            split2(s[2 * ks + 1][0], s[2 * ks + 1][1], aph[2], apl[2]);
            split2(s[2 * ks + 1][2], s[2 * ks + 1][3], aph[3], apl[3]);
            int vr = ks * 16 + (lane & 7) + 8 * ((lane >> 3) & 1);
#pragma unroll
            for (int g = 0; g < 4; g++) {
                int chk = g * 2 + (lane >> 4);
                uint32_t vh[4], vl[4];
                ldsm4t(vh, SWADDR(sVh, vr, chk));
                ldsm4t(vl, SWADDR(sVl, vr, chk));
                float* c0 = o[g * 2 + 0];
                float* c1 = o[g * 2 + 1];
                mma16816(c0, aph, vh[0], vh[1]);
                mma16816(c0, aph, vl[0], vl[1]);
                mma16816(c0, apl, vh[0], vh[1]);
                mma16816(c1, aph, vh[2], vh[3]);
                mma16816(c1, aph, vl[2], vl[3]);
                mma16816(c1, apl, vh[2], vh[3]);
            }
        }
        __syncthreads();
        if (kb + 2 < NKB) load_kv(kb + 2, kb & 1);
    }

    // ---- epilogue: normalize, split, write AO -----------------------------
    float inv0 = 1.f / l0, inv1 = 1.f / l1;
#pragma unroll
    for (int na = 0; na < 8; na++) {
        int col = h * HDIM + na * 8 + (lane & 3) * 2;
        int row0 = qrow0 + w * 16 + (lane >> 2);
        uint32_t hi, lo;
        split2(o[na][0] * inv0, o[na][1] * inv0, hi, lo);
        size_t off0 = (size_t)row0 * EMBED + col;
        *(uint32_t*)&Oh[off0] = hi;
        *(uint32_t*)&Ol[off0] = lo;
        split2(o[na][2] * inv1, o[na][3] * inv1, hi, lo);
        size_t off1 = (size_t)(row0 + 8) * EMBED + col;
        *(uint32_t*)&Oh[off1] = hi;
        *(uint32_t*)&Ol[off1] = lo;
    }
}

// ---------------------------------------------------------------------------
extern "C" void kernel_launch(void* const* d_in, const int* in_sizes, int n_in,
                              void* d_out, int out_size)
{
    const float* x  = (const float*)d_in[0];
    const float* Wq = (const float*)d_in[1];
    const float* bq = (const float*)d_in[2];
    const float* Wk = (const float*)d_in[3];
    const float* bk = (const float*)d_in[4];
    const float* Wv = (const float*)d_in[5];
    const float* bv = (const float*)d_in[6];
    const float* Wo = (const float*)d_in[7];
    const float* bo = (const float*)d_in[8];
    float* out = (float*)d_out;

    __nv_bfloat16 *xh, *xl, *wth, *wtl, *qh, *ql, *kh, *kl, *vh, *vl, *aoh, *aol;
    cudaGetSymbolAddress((void**)&xh,  g_xh);
    cudaGetSymbolAddress((void**)&xl,  g_xl);
    cudaGetSymbolAddress((void**)&wth, g_wth);
    cudaGetSymbolAddress((void**)&wtl, g_wtl);
    cudaGetSymbolAddress((void**)&qh,  g_qh);
    cudaGetSymbolAddress((void**)&ql,  g_ql);
    cudaGetSymbolAddress((void**)&kh,  g_kh);
    cudaGetSymbolAddress((void**)&kl,  g_kl);
    cudaGetSymbolAddress((void**)&vh,  g_vh);
    cudaGetSymbolAddress((void**)&vl,  g_vl);
    cudaGetSymbolAddress((void**)&aoh, g_aoh);
    cudaGetSymbolAddress((void**)&aol, g_aol);

    cudaFuncSetAttribute(gemm_mma,
        cudaFuncAttributeMaxDynamicSharedMemorySize, GEMM_SMEM);
    cudaFuncSetAttribute(flash_mma,
        cudaFuncAttributeMaxDynamicSharedMemorySize, FL_SMEM);

    const size_t WSZ = (size_t)EMBED * EMBED;
    const float* Ws[4] = {Wq, Wk, Wv, Wo};

    split_f32<<<(MTOT * EMBED / 4 + 255) / 256, 256>>>(x, xh, xl, MTOT * EMBED / 4);
    dim3 tg(EMBED / 32, EMBED / 32);
    for (int wi = 0; wi < 4; wi++)
        transpose_split<<<tg, dim3(32, 8)>>>(Ws[wi], wth + wi * WSZ, wtl + wi * WSZ);

    dim3 gg(EMBED / 128, MTOT / 128);   // (8, 32)
    gemm_mma<<<gg, 512, GEMM_SMEM>>>(xh, xl, wth + 0 * WSZ, wtl + 0 * WSZ,
                                     bq, nullptr, qh, ql, MTOT, EMBED, EMBED);
    gemm_mma<<<gg, 512, GEMM_SMEM>>>(xh, xl, wth + 1 * WSZ, wtl + 1 * WSZ,
                                     bk, nullptr, kh, kl, MTOT, EMBED, EMBED);
    gemm_mma<<<gg, 512, GEMM_SMEM>>>(xh, xl, wth + 2 * WSZ, wtl + 2 * WSZ,
                                     bv, nullptr, vh, vl, MTOT, EMBED, EMBED);

    flash_mma<<<dim3(SEQ / 128, HEADS, BATCH), 256, FL_SMEM>>>(
        qh, ql, kh, kl, vh, vl, aoh, aol);

    gemm_mma<<<gg, 512, GEMM_SMEM>>>(aoh, aol, wth + 3 * WSZ, wtl + 3 * WSZ,
                                     bo, out, nullptr, nullptr, MTOT, EMBED, EMBED);
}

// round 7
// speedup vs baseline: 3.1586x; 1.1550x over previous
#include <cuda_runtime.h>
#include <cuda_bf16.h>
#include <math.h>
#include <stdint.h>

#define EMBED 1024
#define HEADS 16
#define HDIM  64
#define BATCH 2
#define SEQ   2048
#define MTOT  (BATCH*SEQ)   // 4096
#define WSZ   ((size_t)EMBED*EMBED)

// ---------------- scratch (device globals; no allocation allowed) ----------
__device__ __nv_bfloat16 g_xh[MTOT*EMBED],  g_xl[MTOT*EMBED];
__device__ __nv_bfloat16 g_wth[4][EMBED*EMBED];
__device__ __nv_bfloat16 g_wtl[4][EMBED*EMBED];
__device__ __nv_bfloat16 g_qh[MTOT*EMBED], g_ql[MTOT*EMBED];
__device__ __nv_bfloat16 g_kh[MTOT*EMBED], g_kl[MTOT*EMBED];
__device__ __nv_bfloat16 g_vh[MTOT*EMBED], g_vl[MTOT*EMBED];
__device__ __nv_bfloat16 g_aoh[MTOT*EMBED], g_aol[MTOT*EMBED];

// ---------------- baseline-ISA PTX helpers ---------------------------------
__device__ __forceinline__ uint32_t smem_u32(const void* p) {
    uint32_t a;
    asm("{ .reg .u64 t; cvta.to.shared.u64 t, %1; cvt.u32.u64 %0, t; }"
        : "=r"(a) : "l"(p));
    return a;
}
__device__ __forceinline__ void ldsm4(uint32_t* r, uint32_t addr) {
    asm volatile("ldmatrix.sync.aligned.m8n8.x4.shared.b16 {%0,%1,%2,%3}, [%4];"
        : "=r"(r[0]), "=r"(r[1]), "=r"(r[2]), "=r"(r[3]) : "r"(addr));
}
__device__ __forceinline__ void ldsm4t(uint32_t* r, uint32_t addr) {
    asm volatile("ldmatrix.sync.aligned.m8n8.x4.trans.shared.b16 {%0,%1,%2,%3}, [%4];"
        : "=r"(r[0]), "=r"(r[1]), "=r"(r[2]), "=r"(r[3]) : "r"(addr));
}
__device__ __forceinline__ void mma16816(float* c, const uint32_t* a,
                                         uint32_t b0, uint32_t b1) {
    asm volatile("mma.sync.aligned.m16n8k16.row.col.f32.bf16.bf16.f32 "
        "{%0,%1,%2,%3}, {%4,%5,%6,%7}, {%8,%9}, {%0,%1,%2,%3};"
        : "+f"(c[0]), "+f"(c[1]), "+f"(c[2]), "+f"(c[3])
        : "r"(a[0]), "r"(a[1]), "r"(a[2]), "r"(a[3]), "r"(b0), "r"(b1));
}
__device__ __forceinline__ void cpa16(uint32_t dst, const void* src) {
    asm volatile("cp.async.cg.shared.global [%0], [%1], 16;"
                 :: "r"(dst), "l"(src));
}
#define CP_COMMIT() asm volatile("cp.async.commit_group;" ::: "memory")
#define CP_WAIT1()  asm volatile("cp.async.wait_group 1;" ::: "memory")
#define CP_WAIT0()  asm volatile("cp.async.wait_group 0;" ::: "memory")

// swizzled smem offset inside a 128B-row tile: (row, 16B-chunk)
#define SWADDR(base, row, chk) ((base) + (row)*128 + ((((chk) ^ ((row)&7))) << 4))

// split two fp32 -> packed bf16x2 hi + lo
__device__ __forceinline__ void split2(float v0, float v1,
                                       uint32_t& hi, uint32_t& lo) {
    __nv_bfloat16 h0 = __float2bfloat16(v0), h1 = __float2bfloat16(v1);
    float r0 = v0 - __bfloat162float(h0);
    float r1 = v1 - __bfloat162float(h1);
    __nv_bfloat162 H; H.x = h0; H.y = h1;
    __nv_bfloat162 L; L.x = __float2bfloat16(r0); L.y = __float2bfloat16(r1);
    hi = *(uint32_t*)&H;
    lo = *(uint32_t*)&L;
}

// ---------------------------------------------------------------------------
// prep kernels
// ---------------------------------------------------------------------------
__global__ __launch_bounds__(256) void split_f32(
    const float* __restrict__ src, __nv_bfloat16* __restrict__ hi,
    __nv_bfloat16* __restrict__ lo, int n4)
{
    int i = blockIdx.x * 256 + threadIdx.x;
    if (i >= n4) return;
    float4 v = ((const float4*)src)[i];
    uint32_t h01, l01, h23, l23;
    split2(v.x, v.y, h01, l01);
    split2(v.z, v.w, h23, l23);
    uint2 H = {h01, h23}, L = {l01, l23};
    ((uint2*)hi)[i] = H;
    ((uint2*)lo)[i] = L;
}

// transpose all 4 weights in one launch: z selects W
__global__ __launch_bounds__(256) void transpose_split4(
    const float* __restrict__ W0, const float* __restrict__ W1,
    const float* __restrict__ W2, const float* __restrict__ W3,
    __nv_bfloat16* __restrict__ ThB, __nv_bfloat16* __restrict__ TlB)
{
    __shared__ float t[32][33];
    int z = blockIdx.z;
    const float* W = (z == 0) ? W0 : (z == 1) ? W1 : (z == 2) ? W2 : W3;
    __nv_bfloat16* Th = ThB + z * WSZ;
    __nv_bfloat16* Tl = TlB + z * WSZ;
    int n0 = blockIdx.x * 32, k0 = blockIdx.y * 32;
    int tx = threadIdx.x, ty = threadIdx.y;
#pragma unroll
    for (int i = 0; i < 4; i++) {
        int k = ty + i * 8;
        t[k][tx] = W[(size_t)(k0 + k) * EMBED + n0 + tx];
    }
    __syncthreads();
#pragma unroll
    for (int i = 0; i < 4; i++) {
        int n = ty + i * 8;
        float v = t[tx][n];
        __nv_bfloat16 h = __float2bfloat16(v);
        __nv_bfloat16 l = __float2bfloat16(v - __bfloat162float(h));
        size_t o = (size_t)(n0 + n) * EMBED + k0 + tx;
        Th[o] = h;
        Tl[o] = l;
    }
}

// ---------------------------------------------------------------------------
// GEMM via mma.sync bf16 split:  C[M,N] = (Ah+Al) @ (Wh+Wl)^T + bias
// CTA tile 128(M) x 64(N), BK=64, 256 threads (8 warps: 2m x 4n), 2-stage.
// blockIdx.z selects among up to 3 fused sub-GEMMs (QKV) sharing A.
// smem/stage: Ah 16K | Al 16K | Bh 8K | Bl 8K = 48KB; x2 = 96KB -> 2 CTA/SM.
// ---------------------------------------------------------------------------
#define GEMM_SMEM (2 * 49152)
extern __shared__ char dynsm[];

__global__ __launch_bounds__(256, 2) void gemm_mma(
    const __nv_bfloat16* __restrict__ Ah, const __nv_bfloat16* __restrict__ Al,
    const __nv_bfloat16* __restrict__ WhB, const __nv_bfloat16* __restrict__ WlB,
    const float* __restrict__ b0, const float* __restrict__ b1,
    const float* __restrict__ b2,
    float* __restrict__ Cf,
    __nv_bfloat16* __restrict__ Ch0, __nv_bfloat16* __restrict__ Cl0,
    __nv_bfloat16* __restrict__ Ch1, __nv_bfloat16* __restrict__ Cl1,
    __nv_bfloat16* __restrict__ Ch2, __nv_bfloat16* __restrict__ Cl2)
{
    const int K = EMBED, N = EMBED;
    uint32_t sb = smem_u32(dynsm);
    int tid = threadIdx.x;
    int lane = tid & 31, w = tid >> 5;
    int wm = w >> 2, wn = w & 3;        // 2 x 4 warps
    int bm = blockIdx.y * 128, bn = blockIdx.x * 64;
    int z = blockIdx.z;

    const __nv_bfloat16* Wh = WhB + (size_t)z * WSZ;
    const __nv_bfloat16* Wl = WlB + (size_t)z * WSZ;
    const float* bias = (z == 0) ? b0 : (z == 1) ? b1 : b2;
    __nv_bfloat16* Ch = (z == 0) ? Ch0 : (z == 1) ? Ch1 : Ch2;
    __nv_bfloat16* Cl = (z == 0) ? Cl0 : (z == 1) ? Cl1 : Cl2;

    auto load_chunk = [&](int ci, int st) {
        uint32_t stb = sb + st * 49152;
#pragma unroll
        for (int rep = 0; rep < 8; rep++) {            // A tiles: 2048 x 16B
            int idx = rep * 256 + tid;
            int tile = idx >> 10;                      // 0 = Ah, 1 = Al
            int row = (idx >> 3) & 127;
            int c = idx & 7;
            const char* src = (const char*)(tile ? Al : Ah)
                + ((size_t)(bm + row) * K + ci * 64) * 2 + c * 16;
            cpa16(SWADDR(stb + tile * 16384, row, c), src);
        }
#pragma unroll
        for (int rep = 0; rep < 4; rep++) {            // B tiles: 1024 x 16B
            int j = rep * 256 + tid;
            int tile = j >> 9;                         // 0 = Bh, 1 = Bl
            int row = (j >> 3) & 63;
            int c = j & 7;
            const char* src = (const char*)(tile ? Wl : Wh)
                + ((size_t)(bn + row) * K + ci * 64) * 2 + c * 16;
            cpa16(SWADDR(stb + 32768 + tile * 8192, row, c), src);
        }
        CP_COMMIT();
    };

    float acc[4][2][4];
#pragma unroll
    for (int a = 0; a < 4; a++)
#pragma unroll
        for (int b = 0; b < 2; b++)
#pragma unroll
            for (int c = 0; c < 4; c++) acc[a][b][c] = 0.f;

    const int NCH = K / 64;   // 16
    load_chunk(0, 0);
    load_chunk(1, 1);

    for (int i = 0; i < NCH; i++) {
        if (i < NCH - 1) CP_WAIT1(); else CP_WAIT0();
        __syncthreads();
        uint32_t stb = sb + (i & 1) * 49152;
        uint32_t sAh = stb, sAl = stb + 16384, sBh = stb + 32768, sBl = stb + 40960;

#pragma unroll
        for (int ks = 0; ks < 4; ks++) {
            int chk = ks * 2 + (lane >> 4);
            uint32_t bh[4], bl[4];
            int br = wn * 16 + (lane & 15);
            ldsm4(bh, SWADDR(sBh, br, chk));
            ldsm4(bl, SWADDR(sBl, br, chk));
#pragma unroll
            for (int ma = 0; ma < 4; ma++) {
                uint32_t ah[4], al[4];
                int r = wm * 64 + ma * 16 + (lane & 15);
                ldsm4(ah, SWADDR(sAh, r, chk));
                ldsm4(al, SWADDR(sAl, r, chk));
                float* c0 = acc[ma][0];
                float* c1 = acc[ma][1];
                mma16816(c0, ah, bh[0], bh[2]);
                mma16816(c0, ah, bl[0], bl[2]);
                mma16816(c0, al, bh[0], bh[2]);
                mma16816(c1, ah, bh[1], bh[3]);
                mma16816(c1, ah, bl[1], bl[3]);
                mma16816(c1, al, bh[1], bh[3]);
            }
        }
        __syncthreads();
        if (i + 2 < NCH) load_chunk(i + 2, i & 1);
    }

    // epilogue
#pragma unroll
    for (int n8 = 0; n8 < 2; n8++) {
        int col = bn + wn * 16 + n8 * 8 + (lane & 3) * 2;
        float bb0 = bias[col], bb1 = bias[col + 1];
#pragma unroll
        for (int ma = 0; ma < 4; ma++) {
            int row0 = bm + wm * 64 + ma * 16 + (lane >> 2);
#pragma unroll
            for (int ri = 0; ri < 2; ri++) {
                int row = row0 + ri * 8;
                float v0 = acc[ma][n8][ri * 2 + 0] + bb0;
                float v1 = acc[ma][n8][ri * 2 + 1] + bb1;
                size_t off = (size_t)row * N + col;
                if (Cf) {
                    float2 o = {v0, v1};
                    *(float2*)&Cf[off] = o;
                } else {
                    uint32_t hi, lo;
                    split2(v0, v1, hi, lo);
                    *(uint32_t*)&Ch[off] = hi;
                    *(uint32_t*)&Cl[off] = lo;
                }
            }
        }
    }
}

// ---------------------------------------------------------------------------
// Flash attention via mma.sync bf16 split (same math as round 5).
// 256 threads, 8 warps; warp = 16 q rows; key blocks of 64.
// smem: Qh 16K | Ql 16K | 2 stages x (Kh Kl Vh Vl, 8K each) = 96KB -> 2 CTA/SM
// ---------------------------------------------------------------------------
#define FL_SMEM (32768 + 2 * 32768)

__global__ __launch_bounds__(256, 2) void flash_mma(
    const __nv_bfloat16* __restrict__ Qh, const __nv_bfloat16* __restrict__ Ql,
    const __nv_bfloat16* __restrict__ Kh, const __nv_bfloat16* __restrict__ Kl,
    const __nv_bfloat16* __restrict__ Vh, const __nv_bfloat16* __restrict__ Vl,
    __nv_bfloat16* __restrict__ Oh, __nv_bfloat16* __restrict__ Ol)
{
    uint32_t sb = smem_u32(dynsm);
    int tid = threadIdx.x;
    int lane = tid & 31, w = tid >> 5;
    int qt = blockIdx.x, h = blockIdx.y, b = blockIdx.z;
    int qrow0 = b * SEQ + qt * 128;
    int krow0 = b * SEQ;
    size_t hoff = (size_t)h * HDIM;

    uint32_t sQh = sb, sQl = sb + 16384;
    const __nv_bfloat16* kvsrc[4] = {Kh, Kl, Vh, Vl};

    auto load_kv = [&](int kb, int st) {
        uint32_t stb = sb + 32768 + st * 32768;
#pragma unroll
        for (int rep = 0; rep < 8; rep++) {
            int idx = rep * 256 + tid;
            int tile = idx >> 9;
            int row = (idx >> 3) & 63;
            int c = idx & 7;
            const char* src = (const char*)kvsrc[tile]
                + ((size_t)(krow0 + kb * 64 + row) * EMBED + hoff) * 2 + c * 16;
            cpa16(SWADDR(stb + tile * 8192, row, c), src);
        }
        CP_COMMIT();
    };

    {
#pragma unroll
        for (int rep = 0; rep < 8; rep++) {
            int idx = rep * 256 + tid;
            int tile = idx >> 10;            // 0 = Qh, 1 = Ql
            int row = (idx >> 3) & 127;
            int c = idx & 7;
            const char* src = (const char*)(tile ? Ql : Qh)
                + ((size_t)(qrow0 + row) * EMBED + hoff) * 2 + c * 16;
            cpa16(SWADDR(sb + tile * 16384, row, c), src);
        }
#pragma unroll
        for (int rep = 0; rep < 8; rep++) {
            int idx = rep * 256 + tid;
            int tile = idx >> 9;
            int row = (idx >> 3) & 63;
            int c = idx & 7;
            const char* src = (const char*)kvsrc[tile]
                + ((size_t)(krow0 + row) * EMBED + hoff) * 2 + c * 16;
            cpa16(SWADDR(sb + 32768 + tile * 8192, row, c), src);
        }
        CP_COMMIT();
    }
    load_kv(1, 1);

    float o[8][4];
#pragma unroll
    for (int a = 0; a < 8; a++)
#pragma unroll
        for (int c = 0; c < 4; c++) o[a][c] = 0.f;
    float m0 = -1e30f, m1 = -1e30f, l0 = 0.f, l1 = 0.f;

    const int NKB = SEQ / 64;   // 32
    for (int kb = 0; kb < NKB; kb++) {
        if (kb < NKB - 1) CP_WAIT1(); else CP_WAIT0();
        __syncthreads();
        uint32_t stb = sb + 32768 + (kb & 1) * 32768;
        uint32_t sKh = stb, sKl = stb + 8192, sVh = stb + 16384, sVl = stb + 24576;

        float s[8][4];
#pragma unroll
        for (int a = 0; a < 8; a++)
#pragma unroll
            for (int c = 0; c < 4; c++) s[a][c] = 0.f;

#pragma unroll
        for (int ks = 0; ks < 4; ks++) {
            int chk = ks * 2 + (lane >> 4);
            int ar = w * 16 + (lane & 15);
            uint32_t qh[4], ql[4];
            ldsm4(qh, SWADDR(sQh, ar, chk));
            ldsm4(ql, SWADDR(sQl, ar, chk));
#pragma unroll
            for (int np = 0; np < 4; np++) {
                int br = np * 16 + (lane & 15);
                uint32_t bh[4], bl[4];
                ldsm4(bh, SWADDR(sKh, br, chk));
                ldsm4(bl, SWADDR(sKl, br, chk));
                float* c0 = s[np * 2 + 0];
                float* c1 = s[np * 2 + 1];
                mma16816(c0, qh, bh[0], bh[2]);
                mma16816(c0, qh, bl[0], bl[2]);
                mma16816(c0, ql, bh[0], bh[2]);
                mma16816(c1, qh, bh[1], bh[3]);
                mma16816(c1, qh, bl[1], bl[3]);
                mma16816(c1, ql, bh[1], bh[3]);
            }
        }

#pragma unroll
        for (int a = 0; a < 8; a++)
#pragma unroll
            for (int c = 0; c < 4; c++) s[a][c] *= 0.125f;

        float mx0 = -1e30f, mx1 = -1e30f;
#pragma unroll
        for (int a = 0; a < 8; a++) {
            mx0 = fmaxf(mx0, fmaxf(s[a][0], s[a][1]));
            mx1 = fmaxf(mx1, fmaxf(s[a][2], s[a][3]));
        }
        mx0 = fmaxf(mx0, __shfl_xor_sync(0xffffffffu, mx0, 1));
        mx0 = fmaxf(mx0, __shfl_xor_sync(0xffffffffu, mx0, 2));
        mx1 = fmaxf(mx1, __shfl_xor_sync(0xffffffffu, mx1, 1));
        mx1 = fmaxf(mx1, __shfl_xor_sync(0xffffffffu, mx1, 2));
        float mn0 = fmaxf(m0, mx0), mn1 = fmaxf(m1, mx1);
        float cr0 = __expf(m0 - mn0), cr1 = __expf(m1 - mn1);
        m0 = mn0; m1 = mn1;
        float sum0 = 0.f, sum1 = 0.f;
#pragma unroll
        for (int a = 0; a < 8; a++) {
            s[a][0] = __expf(s[a][0] - mn0); sum0 += s[a][0];
            s[a][1] = __expf(s[a][1] - mn0); sum0 += s[a][1];
            s[a][2] = __expf(s[a][2] - mn1); sum1 += s[a][2];
            s[a][3] = __expf(s[a][3] - mn1); sum1 += s[a][3];
        }
        sum0 += __shfl_xor_sync(0xffffffffu, sum0, 1);
        sum0 += __shfl_xor_sync(0xffffffffu, sum0, 2);
        sum1 += __shfl_xor_sync(0xffffffffu, sum1, 1);
        sum1 += __shfl_xor_sync(0xffffffffu, sum1, 2);
        l0 = l0 * cr0 + sum0;
        l1 = l1 * cr1 + sum1;
#pragma unroll
        for (int a = 0; a < 8; a++) {
            o[a][0] *= cr0; o[a][1] *= cr0;
            o[a][2] *= cr1; o[a][3] *= cr1;
        }

#pragma unroll
        for (int ks = 0; ks < 4; ks++) {
            uint32_t aph[4], apl[4];
            split2(s[2 * ks][0],     s[2 * ks][1],     aph[0], apl[0]);
            split2(s[2 * ks][2],     s[2 * ks][3],     aph[1], apl[1]);
            split2(s[2 * ks + 1][0], s[2 * ks + 1][1], aph[2], apl[2]);
            split2(s[2 * ks + 1][2], s[2 * ks + 1][3], aph[3], apl[3]);
            int vr = ks * 16 + (lane & 7) + 8 * ((lane >> 3) & 1);
#pragma unroll
            for (int g = 0; g < 4; g++) {
                int chk = g * 2 + (lane >> 4);
                uint32_t vh[4], vl[4];
                ldsm4t(vh, SWADDR(sVh, vr, chk));
                ldsm4t(vl, SWADDR(sVl, vr, chk));
                float* c0 = o[g * 2 + 0];
                float* c1 = o[g * 2 + 1];
                mma16816(c0, aph, vh[0], vh[1]);
                mma16816(c0, aph, vl[0], vl[1]);
                mma16816(c0, apl, vh[0], vh[1]);
                mma16816(c1, aph, vh[2], vh[3]);
                mma16816(c1, aph, vl[2], vl[3]);
                mma16816(c1, apl, vh[2], vh[3]);
            }
        }
        __syncthreads();
        if (kb + 2 < NKB) load_kv(kb + 2, kb & 1);
    }

    float inv0 = 1.f / l0, inv1 = 1.f / l1;
#pragma unroll
    for (int na = 0; na < 8; na++) {
        int col = h * HDIM + na * 8 + (lane & 3) * 2;
        int row0 = qrow0 + w * 16 + (lane >> 2);
        uint32_t hi, lo;
        split2(o[na][0] * inv0, o[na][1] * inv0, hi, lo);
        size_t off0 = (size_t)row0 * EMBED + col;
        *(uint32_t*)&Oh[off0] = hi;
        *(uint32_t*)&Ol[off0] = lo;
        split2(o[na][2] * inv1, o[na][3] * inv1, hi, lo);
        size_t off1 = (size_t)(row0 + 8) * EMBED + col;
        *(uint32_t*)&Oh[off1] = hi;
        *(uint32_t*)&Ol[off1] = lo;
    }
}

// ---------------------------------------------------------------------------
extern "C" void kernel_launch(void* const* d_in, const int* in_sizes, int n_in,
                              void* d_out, int out_size)
{
    const float* x  = (const float*)d_in[0];
    const float* Wq = (const float*)d_in[1];
    const float* bq = (const float*)d_in[2];
    const float* Wk = (const float*)d_in[3];
    const float* bk = (const float*)d_in[4];
    const float* Wv = (const float*)d_in[5];
    const float* bv = (const float*)d_in[6];
    const float* Wo = (const float*)d_in[7];
    const float* bo = (const float*)d_in[8];
    float* out = (float*)d_out;

    __nv_bfloat16 *xh, *xl, *wth, *wtl, *qh, *ql, *kh, *kl, *vh, *vl, *aoh, *aol;
    cudaGetSymbolAddress((void**)&xh,  g_xh);
    cudaGetSymbolAddress((void**)&xl,  g_xl);
    cudaGetSymbolAddress((void**)&wth, g_wth);
    cudaGetSymbolAddress((void**)&wtl, g_wtl);
    cudaGetSymbolAddress((void**)&qh,  g_qh);
    cudaGetSymbolAddress((void**)&ql,  g_ql);
    cudaGetSymbolAddress((void**)&kh,  g_kh);
    cudaGetSymbolAddress((void**)&kl,  g_kl);
    cudaGetSymbolAddress((void**)&vh,  g_vh);
    cudaGetSymbolAddress((void**)&vl,  g_vl);
    cudaGetSymbolAddress((void**)&aoh, g_aoh);
    cudaGetSymbolAddress((void**)&aol, g_aol);

    cudaFuncSetAttribute(gemm_mma,
        cudaFuncAttributeMaxDynamicSharedMemorySize, GEMM_SMEM);
    cudaFuncSetAttribute(flash_mma,
        cudaFuncAttributeMaxDynamicSharedMemorySize, FL_SMEM);

    split_f32<<<(MTOT * EMBED / 4 + 255) / 256, 256>>>(x, xh, xl, MTOT * EMBED / 4);
    transpose_split4<<<dim3(EMBED / 32, EMBED / 32, 4), dim3(32, 8)>>>(
        Wq, Wk, Wv, Wo, wth, wtl);

    // fused Q/K/V projections
    gemm_mma<<<dim3(EMBED / 64, MTOT / 128, 3), 256, GEMM_SMEM>>>(
        xh, xl, wth, wtl, bq, bk, bv,
        nullptr, qh, ql, kh, kl, vh, vl);

    flash_mma<<<dim3(SEQ / 128, HEADS, BATCH), 256, FL_SMEM>>>(
        qh, ql, kh, kl, vh, vl, aoh, aol);

    // output projection (fp32 out): z=0 selects W index 3 via offset base
    gemm_mma<<<dim3(EMBED / 64, MTOT / 128, 1), 256, GEMM_SMEM>>>(
        aoh, aol, wth + 3 * WSZ, wtl + 3 * WSZ, bo, bo, bo,
        out, nullptr, nullptr, nullptr, nullptr, nullptr, nullptr);
}